// round 4
// baseline (speedup 1.0000x reference)
#include <cuda_runtime.h>
#include <stdint.h>

#define Bn 8
#define Hn 1024
#define Wn 1024
#define HW (Hn * Wn)
#define Nn (Bn * Hn * Wn)
#define THRESH 1.5f
#define MIN_AREA_C 3
#define TPB 256
#define PPT 4                       // pixels/thread: init, merge, aggregate
#define EPT 8                       // pixels/thread: emit
#define NT4 (Nn / PPT)
#define NT8 (Nn / EPT)

// Scratch in __device__ globals (no runtime allocation allowed).
__device__ int                g_parent[Nn];   // fg: union-find parent; bg: -1
__device__ unsigned long long g_agg[Nn];      // packed (val_bits<<32) | ~within
__device__ int                g_area[Nn];     // per-root pixel count

__device__ __forceinline__ unsigned long long pack_key(float v, int i) {
    unsigned int vb     = (unsigned int)__float_as_int(v);        // v>=1.5>0
    unsigned int within = (unsigned int)(i & (HW - 1));
    return ((unsigned long long)vb << 32) | (unsigned long long)(~within);
}

// ---------------------------------------------------------------------------
// Union-find. Roots only decrease (atomicMin links high -> low), so read-only
// find is race-safe during merge.
// ---------------------------------------------------------------------------
__device__ __forceinline__ int find_ro(int i) {
    int p;
    while ((p = g_parent[i]) != i) i = p;
    return i;
}

__device__ __forceinline__ void unite(int a, int b) {
    int ra = find_ro(a);
    int rb = find_ro(b);
    while (ra != rb) {
        if (ra < rb) { int t = ra; ra = rb; rb = t; }  // ra > rb
        int old = atomicMin(&g_parent[ra], rb);
        if (old == ra) break;
        ra = find_ro(old);
        rb = find_ro(rb);
    }
}

// ---------------------------------------------------------------------------
// K0: threshold + init. Pre-seed agg with the pixel's own key (so the
// aggregate pass never needs x again); area=0. Only fg entries touched.
// ---------------------------------------------------------------------------
__global__ void k_init(const float* __restrict__ x) {
    int t = blockIdx.x * blockDim.x + threadIdx.x;
    if (t >= NT4) return;
    int base = t * PPT;
    float4 v = *reinterpret_cast<const float4*>(x + base);
    int4 p;
    p.x = (v.x >= THRESH) ? base     : -1;
    p.y = (v.y >= THRESH) ? base + 1 : -1;
    p.z = (v.z >= THRESH) ? base + 2 : -1;
    p.w = (v.w >= THRESH) ? base + 3 : -1;
    *reinterpret_cast<int4*>(g_parent + base) = p;
    if (p.x >= 0) { g_agg[base]     = pack_key(v.x, base);     g_area[base]     = 0; }
    if (p.y >= 0) { g_agg[base + 1] = pack_key(v.y, base + 1); g_area[base + 1] = 0; }
    if (p.z >= 0) { g_agg[base + 2] = pack_key(v.z, base + 2); g_area[base + 2] = 0; }
    if (p.w >= 0) { g_agg[base + 3] = pack_key(v.w, base + 3); g_area[base + 3] = 0; }
}

// ---------------------------------------------------------------------------
// K1: union with backward 8-neighbors. int4 covers this run + the row above;
// left neighbor from register chain. Komura pruning: if 'up' fg, skip the
// diagonals (connected through up via row-wise left unions).
// ---------------------------------------------------------------------------
__global__ void k_merge() {
    int t = blockIdx.x * blockDim.x + threadIdx.x;
    if (t >= NT4) return;
    int base = t * PPT;
    int c0 = base & (Wn - 1);
    int r  = (base >> 10) & (Hn - 1);

    int4 pc = *reinterpret_cast<const int4*>(g_parent + base);
    int fgc[PPT] = { pc.x >= 0, pc.y >= 0, pc.z >= 0, pc.w >= 0 };
    if (!(fgc[0] | fgc[1] | fgc[2] | fgc[3])) return;

    int up[PPT + 2];   // up[k] = parent[base - Wn + (k-1)]
    if (r > 0) {
        int4 pu = *reinterpret_cast<const int4*>(g_parent + base - Wn);
        up[1] = pu.x; up[2] = pu.y; up[3] = pu.z; up[4] = pu.w;
        up[0] = (c0 > 0)        ? g_parent[base - Wn - 1] : -1;
        up[5] = (c0 < Wn - PPT) ? g_parent[base - Wn + 4] : -1;
    } else {
        up[0] = up[1] = up[2] = up[3] = up[4] = up[5] = -1;
    }
    int pl = (c0 > 0) ? g_parent[base - 1] : -1;
    int lf[PPT] = { pl >= 0, fgc[0], fgc[1], fgc[2] };

    #pragma unroll
    for (int k = 0; k < PPT; k++) {
        if (!fgc[k]) continue;
        int i = base + k;
        if (lf[k]) unite(i, i - 1);
        if (up[k + 1] >= 0) {
            unite(i, i - Wn);
        } else {
            if (up[k] >= 0)     unite(i, i - Wn - 1);
            if (up[k + 2] >= 0) unite(i, i - Wn + 1);
        }
    }
}

// ---------------------------------------------------------------------------
// K2: aggregate. Key comes from the pre-seeded agg[i] (L2-resident) — no x
// read. No compression write-back (emit chases the short trees itself).
// ---------------------------------------------------------------------------
__global__ void k_aggregate() {
    int t = blockIdx.x * blockDim.x + threadIdx.x;
    if (t >= NT4) return;
    int base = t * PPT;
    int4 pc = *reinterpret_cast<const int4*>(g_parent + base);
    int pv[PPT] = { pc.x, pc.y, pc.z, pc.w };
    if (pv[0] < 0 && pv[1] < 0 && pv[2] < 0 && pv[3] < 0) return;

    int roots[PPT];
    #pragma unroll
    for (int k = 0; k < PPT; k++)
        roots[k] = (pv[k] >= 0) ? find_ro(base + k) : -1;

    #pragma unroll
    for (int k = 0; k < PPT; k++) {
        if (roots[k] < 0) continue;
        int i = base + k;
        atomicAdd(&g_area[roots[k]], 1);
        if (roots[k] != i) {
            unsigned long long key = g_agg[i];   // seeded in k_init; stable now
            atomicMax(&g_agg[roots[k]], key);
        }
    }
}

// ---------------------------------------------------------------------------
// K3: emit dense (max,row,col) float32, 8 px/thread, float4 stores. Chases
// the (shallow, L2-resident) parent trees itself.
// ---------------------------------------------------------------------------
__global__ void k_emit(float* __restrict__ out, int write_rc) {
    int t = blockIdx.x * blockDim.x + threadIdx.x;
    if (t >= NT8) return;
    int base = t * EPT;
    int4 pa = *reinterpret_cast<const int4*>(g_parent + base);
    int4 pb = *reinterpret_cast<const int4*>(g_parent + base + 4);
    int pv[EPT] = { pa.x, pa.y, pa.z, pa.w, pb.x, pb.y, pb.z, pb.w };

    // chase to roots (independent chains -> MLP)
    int rt[EPT];
    #pragma unroll
    for (int k = 0; k < EPT; k++) {
        int r = pv[k];
        if (r >= 0) {
            int p;
            while ((p = __ldg(&g_parent[r])) != r) r = p;
        }
        rt[k] = r;
    }
    int ar[EPT];
    #pragma unroll
    for (int k = 0; k < EPT; k++)
        ar[k] = (rt[k] >= 0) ? __ldg(&g_area[rt[k]]) : 0;

    float mx[EPT], rw[EPT], cl[EPT];
    #pragma unroll
    for (int k = 0; k < EPT; k++) {
        mx[k] = 0.0f; rw[k] = -1.0f; cl[k] = -1.0f;
        if (rt[k] >= 0 && ar[k] > MIN_AREA_C) {
            unsigned long long key = __ldg(&g_agg[rt[k]]);
            mx[k] = __int_as_float((int)(unsigned int)(key >> 32));
            unsigned int within = ~(unsigned int)(key & 0xFFFFFFFFull);
            rw[k] = (float)(within >> 10);
            cl[k] = (float)(within & (Wn - 1));
        }
    }
    *reinterpret_cast<float4*>(out + base)     = make_float4(mx[0], mx[1], mx[2], mx[3]);
    *reinterpret_cast<float4*>(out + base + 4) = make_float4(mx[4], mx[5], mx[6], mx[7]);
    if (write_rc) {
        *reinterpret_cast<float4*>(out + Nn + base)         = make_float4(rw[0], rw[1], rw[2], rw[3]);
        *reinterpret_cast<float4*>(out + Nn + base + 4)     = make_float4(rw[4], rw[5], rw[6], rw[7]);
        *reinterpret_cast<float4*>(out + 2 * Nn + base)     = make_float4(cl[0], cl[1], cl[2], cl[3]);
        *reinterpret_cast<float4*>(out + 2 * Nn + base + 4) = make_float4(cl[4], cl[5], cl[6], cl[7]);
    }
}

extern "C" void kernel_launch(void* const* d_in, const int* in_sizes, int n_in,
                              void* d_out, int out_size) {
    const float* x = (const float*)d_in[0];
    float* out = (float*)d_out;
    int write_rc = (out_size >= 3 * Nn) ? 1 : 0;

    k_init<<<(NT4 + TPB - 1) / TPB, TPB>>>(x);
    k_merge<<<(NT4 + TPB - 1) / TPB, TPB>>>();
    k_aggregate<<<(NT4 + TPB - 1) / TPB, TPB>>>();
    k_emit<<<(NT8 + TPB - 1) / TPB, TPB>>>(out, write_rc);
}

// round 8
// speedup vs baseline: 1.1198x; 1.1198x over previous
#include <cuda_runtime.h>
#include <stdint.h>

#define Bn 8
#define Hn 1024
#define Wn 1024
#define HW (Hn * Wn)
#define Nn (Bn * Hn * Wn)
#define THRESH 1.5f
#define MIN_AREA_C 3
#define TPB 256
#define PPT 4
#define NT4 (Nn / PPT)

// Scratch in __device__ globals (no runtime allocation allowed).
__device__ int                g_parent[Nn];   // fg: union-find parent; bg: -1
__device__ unsigned long long g_agg[Nn];      // packed (val_bits<<32) | ~within
__device__ int                g_area[Nn];     // per-root pixel count

__device__ __forceinline__ unsigned long long pack_key(float v, int i) {
    unsigned int vb     = (unsigned int)__float_as_int(v);        // v>=1.5>0
    unsigned int within = (unsigned int)(i & (HW - 1));
    return ((unsigned long long)vb << 32) | (unsigned long long)(~within);
}

// ---------------------------------------------------------------------------
// Union-find. Roots only decrease (atomicMin links high -> low), so read-only
// find is race-safe during merge.
// ---------------------------------------------------------------------------
__device__ __forceinline__ int find_ro(int i) {
    int p;
    while ((p = g_parent[i]) != i) i = p;
    return i;
}

__device__ __forceinline__ void unite(int a, int b) {
    int ra = find_ro(a);
    int rb = find_ro(b);
    while (ra != rb) {
        if (ra < rb) { int t = ra; ra = rb; rb = t; }  // ra > rb
        int old = atomicMin(&g_parent[ra], rb);
        if (old == ra) break;
        ra = find_ro(old);
        rb = find_ro(rb);
    }
}

// ---------------------------------------------------------------------------
// K0: threshold + init. Pre-seed agg with the pixel's own key; area=0.
// Only fg entries of agg/area are touched.
// ---------------------------------------------------------------------------
__global__ void k_init(const float* __restrict__ x) {
    int t = blockIdx.x * blockDim.x + threadIdx.x;
    if (t >= NT4) return;
    int base = t * PPT;
    float4 v = *reinterpret_cast<const float4*>(x + base);
    int4 p;
    p.x = (v.x >= THRESH) ? base     : -1;
    p.y = (v.y >= THRESH) ? base + 1 : -1;
    p.z = (v.z >= THRESH) ? base + 2 : -1;
    p.w = (v.w >= THRESH) ? base + 3 : -1;
    *reinterpret_cast<int4*>(g_parent + base) = p;
    if (p.x >= 0) { g_agg[base]     = pack_key(v.x, base);     g_area[base]     = 0; }
    if (p.y >= 0) { g_agg[base + 1] = pack_key(v.y, base + 1); g_area[base + 1] = 0; }
    if (p.z >= 0) { g_agg[base + 2] = pack_key(v.z, base + 2); g_area[base + 2] = 0; }
    if (p.w >= 0) { g_agg[base + 3] = pack_key(v.w, base + 3); g_area[base + 3] = 0; }
}

// ---------------------------------------------------------------------------
// K1: union with backward 8-neighbors. int4 covers this run + row above;
// left neighbor from register chain. Komura pruning: if 'up' fg, skip the
// diagonals (connected through up via row-wise left unions).
// ---------------------------------------------------------------------------
__global__ void k_merge() {
    int t = blockIdx.x * blockDim.x + threadIdx.x;
    if (t >= NT4) return;
    int base = t * PPT;
    int c0 = base & (Wn - 1);
    int r  = (base >> 10) & (Hn - 1);

    int4 pc = *reinterpret_cast<const int4*>(g_parent + base);
    int fgc[PPT] = { pc.x >= 0, pc.y >= 0, pc.z >= 0, pc.w >= 0 };
    if (!(fgc[0] | fgc[1] | fgc[2] | fgc[3])) return;

    int up[PPT + 2];   // up[k] = parent[base - Wn + (k-1)]
    if (r > 0) {
        int4 pu = *reinterpret_cast<const int4*>(g_parent + base - Wn);
        up[1] = pu.x; up[2] = pu.y; up[3] = pu.z; up[4] = pu.w;
        up[0] = (c0 > 0)        ? g_parent[base - Wn - 1] : -1;
        up[5] = (c0 < Wn - PPT) ? g_parent[base - Wn + 4] : -1;
    } else {
        up[0] = up[1] = up[2] = up[3] = up[4] = up[5] = -1;
    }
    int pl = (c0 > 0) ? g_parent[base - 1] : -1;
    int lf[PPT] = { pl >= 0, fgc[0], fgc[1], fgc[2] };

    #pragma unroll
    for (int k = 0; k < PPT; k++) {
        if (!fgc[k]) continue;
        int i = base + k;
        if (lf[k]) unite(i, i - 1);
        if (up[k + 1] >= 0) {
            unite(i, i - Wn);
        } else {
            if (up[k] >= 0)     unite(i, i - Wn - 1);
            if (up[k + 2] >= 0) unite(i, i - Wn + 1);
        }
    }
}

// ---------------------------------------------------------------------------
// K2: aggregate + path compression. Key comes from pre-seeded agg[i] (L2-
// resident) — no x read. Compressed parent written back only when changed.
// ---------------------------------------------------------------------------
__global__ void k_aggregate() {
    int t = blockIdx.x * blockDim.x + threadIdx.x;
    if (t >= NT4) return;
    int base = t * PPT;
    int4 pc = *reinterpret_cast<const int4*>(g_parent + base);
    int pv[PPT] = { pc.x, pc.y, pc.z, pc.w };
    if (pv[0] < 0 && pv[1] < 0 && pv[2] < 0 && pv[3] < 0) return;

    int roots[PPT];
    #pragma unroll
    for (int k = 0; k < PPT; k++)
        roots[k] = (pv[k] >= 0) ? find_ro(base + k) : -1;

    #pragma unroll
    for (int k = 0; k < PPT; k++) {
        if (roots[k] < 0) continue;
        int i = base + k;
        atomicAdd(&g_area[roots[k]], 1);
        if (roots[k] != i)
            atomicMax(&g_agg[roots[k]], g_agg[i]);   // seeded; stable now
    }

    // write back fully-compressed parents only if something changed
    int4 nc = make_int4(roots[0], roots[1], roots[2], roots[3]);
    if (nc.x != pc.x || nc.y != pc.y || nc.z != pc.z || nc.w != pc.w)
        *reinterpret_cast<int4*>(g_parent + base) = nc;
}

// ---------------------------------------------------------------------------
// K3: emit dense (max,row,col) float32, 4 px/thread. Parent is fully
// compressed -> single gather per pixel. Streaming stores keep the 96MB
// output from evicting L2-resident scratch.
// ---------------------------------------------------------------------------
__global__ void k_emit(float* __restrict__ out, int write_rc) {
    int t = blockIdx.x * blockDim.x + threadIdx.x;
    if (t >= NT4) return;
    int base = t * PPT;
    int4 pc = *reinterpret_cast<const int4*>(g_parent + base);
    int pv[PPT] = { pc.x, pc.y, pc.z, pc.w };

    int ar[PPT];
    #pragma unroll
    for (int k = 0; k < PPT; k++)
        ar[k] = (pv[k] >= 0) ? __ldg(&g_area[pv[k]]) : 0;

    float mx[PPT], rw[PPT], cl[PPT];
    #pragma unroll
    for (int k = 0; k < PPT; k++) {
        mx[k] = 0.0f; rw[k] = -1.0f; cl[k] = -1.0f;
        if (pv[k] >= 0 && ar[k] > MIN_AREA_C) {
            unsigned long long key = __ldg(&g_agg[pv[k]]);
            mx[k] = __int_as_float((int)(unsigned int)(key >> 32));
            unsigned int within = ~(unsigned int)(key & 0xFFFFFFFFull);
            rw[k] = (float)(within >> 10);
            cl[k] = (float)(within & (Wn - 1));
        }
    }
    __stcs(reinterpret_cast<float4*>(out + base),
           make_float4(mx[0], mx[1], mx[2], mx[3]));
    if (write_rc) {
        __stcs(reinterpret_cast<float4*>(out + Nn + base),
               make_float4(rw[0], rw[1], rw[2], rw[3]));
        __stcs(reinterpret_cast<float4*>(out + 2 * Nn + base),
               make_float4(cl[0], cl[1], cl[2], cl[3]));
    }
}

extern "C" void kernel_launch(void* const* d_in, const int* in_sizes, int n_in,
                              void* d_out, int out_size) {
    const float* x = (const float*)d_in[0];
    float* out = (float*)d_out;
    const int blocks = (NT4 + TPB - 1) / TPB;
    int write_rc = (out_size >= 3 * Nn) ? 1 : 0;

    k_init<<<blocks, TPB>>>(x);
    k_merge<<<blocks, TPB>>>();
    k_aggregate<<<blocks, TPB>>>();
    k_emit<<<blocks, TPB>>>(out, write_rc);
}